// round 5
// baseline (speedup 1.0000x reference)
#include <cuda_runtime.h>
#include <cstdint>

// ============================================================================
// QuantumNeuralLayer: out = x @ W.T + (b + 0.1*q); q batch-independent.
// 262144x256x64 fp32 GEMM via mma.sync tf32. R5: W fragments moved to
// global/L1 (not SMEM) so SMEM/CTA drops to 80KB -> 2 CTAs/SM; cross-CTA
// overlap hides the per-stage wait+syncthreads bubbles that bound R4.
// ============================================================================

#define INV_SQRT2 0.70710678118654752440f

static constexpr int B_TOTAL = 262144;
static constexpr int KDIM    = 256;
static constexpr int ODIM    = 64;
static constexpr int TILE_M  = 256;                 // 8 warps x 32 rows
static constexpr int NTILES  = B_TOTAL / TILE_M;    // 1024
static constexpr int NTHREADS = 256;

static constexpr int KCHUNK   = 16;                 // floats per stage
static constexpr int STAGES_PER_TILE = KDIM / KCHUNK;  // 16
static constexpr int APITCH   = 20;                 // floats; balanced banks
static constexpr int ASTAGE_F = TILE_M * APITCH;    // 5120 floats = 20 KB
static constexpr int SMEM_F   = 4 * ASTAGE_F;       // 4-slot ring
static constexpr int SMEM_BYTES = SMEM_F * 4;       // 81920 B

__device__ float2 g_Wf2[8192];    // [s(32)][nt(8)][lane(32)] tf32-rounded
__device__ float  g_bias[64];     // b + 0.1*quantum

// ---------------------------------------------------------------------------
__device__ __forceinline__ uint32_t smem_u32(const void* p) {
    uint32_t a;
    asm("{ .reg .u64 t; cvta.to.shared.u64 t, %1; cvt.u32.u64 %0, t; }" : "=r"(a) : "l"(p));
    return a;
}
__device__ __forceinline__ void cp_async16(uint32_t s, const void* g) {
    asm volatile("cp.async.cg.shared.global [%0], [%1], 16;" :: "r"(s), "l"(g));
}
#define CP_COMMIT() asm volatile("cp.async.commit_group;" ::: "memory")
#define CP_WAIT_2() asm volatile("cp.async.wait_group 2;" ::: "memory")

__device__ __forceinline__ uint32_t f2tf32(float f) {
    uint32_t u;
    asm("cvt.rna.tf32.f32 %0, %1;" : "=r"(u) : "f"(f));
    return u;
}

__device__ __forceinline__ void mma_tf32(float c[4], uint32_t a0, uint32_t a1,
                                         uint32_t a2, uint32_t a3,
                                         uint32_t b0, uint32_t b1) {
    asm volatile(
        "mma.sync.aligned.m16n8k8.row.col.f32.tf32.tf32.f32 "
        "{%0,%1,%2,%3}, {%4,%5,%6,%7}, {%8,%9}, {%0,%1,%2,%3};"
        : "+f"(c[0]), "+f"(c[1]), "+f"(c[2]), "+f"(c[3])
        : "r"(a0), "r"(a1), "r"(a2), "r"(a3), "r"(b0), "r"(b1));
}

// ---------------------------------------------------------------------------
// Prep (parallel): block 0 computes bias_eff; blocks 1..32 build W fragments.
// ---------------------------------------------------------------------------
__global__ void qnl_prep_kernel(const float* __restrict__ b,
                                const float* __restrict__ phase,
                                const float* __restrict__ ent,
                                const float* __restrict__ W) {
    const int tid = threadIdx.x;
    if (blockIdx.x == 0) {
        __shared__ float ha[64], hc[64];
        float a = 1.0f, c = 0.0f;
        for (int d = 0; d < 3; d++) {
            if (tid < 64) {
                float ph = phase[d * 64 + tid];
                ha[tid] = (a + c) * INV_SQRT2 * sinf(ph);
                hc[tid] = (a - c) * INV_SQRT2 * cosf(ph);
            }
            __syncthreads();
            if (tid < 64) {
                float sa = 0.0f, sc = 0.0f;
#pragma unroll
                for (int i = 0; i < 64; i++) {
                    float e = ent[i * 64 + tid];
                    sa += ha[i] * e;
                    sc += hc[i] * e;
                }
                a = sa; c = sc;
            }
            __syncthreads();
        }
        if (tid < 64) g_bias[tid] = b[tid] + 0.1f * (a * a + c * c);
    } else {
        int e = (blockIdx.x - 1) * 256 + tid;   // 0..8191
        int le = e & 31;
        int nt = (e >> 5) & 7;
        int s  = e >> 8;
        int n = nt * 8 + (le >> 2);
        int k = s * 8 + (le & 3);
        float2 wf;
        wf.x = __uint_as_float(f2tf32(W[n * KDIM + k]));
        wf.y = __uint_as_float(f2tf32(W[n * KDIM + k + 4]));
        g_Wf2[e] = wf;
    }
}

// ---------------------------------------------------------------------------
// Main GEMM: 2 CTAs/SM, 4-slot cp.async ring, W fragments from L1.
// ---------------------------------------------------------------------------
__global__ void __launch_bounds__(NTHREADS, 2)
qnl_kernel(const float* __restrict__ x, float* __restrict__ out) {
    extern __shared__ float smemf[];
    const uint32_t sb = smem_u32(smemf);
    const int tid  = threadIdx.x;
    const int wid  = tid >> 5;
    const int lane = tid & 31;
    const int grid = gridDim.x;
    const int bid  = blockIdx.x;

    // Warp owns rows [wid*32, wid*32+32); m-frags at +0 and +16.
    const int arow = wid * 32 + (lane >> 2);

    const int ntile_local = (NTILES - bid + grid - 1) / grid;
    const int H = STAGES_PER_TILE * ntile_local;

    // Load stage jq (tile jq>>4, k-chunk jq&15) into ring slot jq&3.
    auto load_stage = [&](int jq) {
        const int tile = bid + (jq >> 4) * grid;
        const float* src = x + (size_t)tile * TILE_M * KDIM + (jq & 15) * KCHUNK;
        const uint32_t abase = sb + (uint32_t)((jq & 3) * ASTAGE_F) * 4;
#pragma unroll
        for (int i = 0; i < 4; i++) {
            int c  = tid + NTHREADS * i;   // 1024 x 16B chunks
            int r  = c >> 2;               // row 0..255
            int kc = c & 3;                // 16B chunk within 16-float chunk
            cp_async16(abase + (uint32_t)(r * APITCH + kc * 4) * 4,
                       src + (size_t)r * KDIM + kc * 4);
        }
        CP_COMMIT();
    };

    load_stage(0);
    load_stage(1);
    load_stage(2);

    // Bias fragment from global (tiny, L1/L2 broadcast).
    float2 bias[8];
#pragma unroll
    for (int nt = 0; nt < 8; nt++) {
        int col = nt * 8 + 2 * (lane & 3);
        bias[nt].x = __ldg(g_bias + col);
        bias[nt].y = __ldg(g_bias + col + 1);
    }

    float acc[2][8][4];
#pragma unroll
    for (int mb = 0; mb < 2; mb++)
#pragma unroll
        for (int nt = 0; nt < 8; nt++)
#pragma unroll
            for (int q = 0; q < 4; q++) acc[mb][nt][q] = 0.0f;

    for (int j = 0; j < H; j++) {
        CP_WAIT_2();       // stage j resident
        __syncthreads();   // visible; slot (j+3)&3 free

        if (j + 3 < H) load_stage(j + 3);
        else CP_COMMIT();  // uniform group accounting

        const float* Ab = smemf + (j & 3) * ASTAGE_F + arow * APITCH + (lane & 3);
        const int sbase = (j & 15) * 2;

#pragma unroll
        for (int sl = 0; sl < 2; sl++) {
            const int ko = sl * 8;
            uint32_t a0 = f2tf32(Ab[ko]);
            uint32_t a1 = f2tf32(Ab[ko + 8 * APITCH]);
            uint32_t a2 = f2tf32(Ab[ko + 4]);
            uint32_t a3 = f2tf32(Ab[ko + 4 + 8 * APITCH]);
            uint32_t b0 = f2tf32(Ab[ko + 16 * APITCH]);
            uint32_t b1 = f2tf32(Ab[ko + 24 * APITCH]);
            uint32_t b2 = f2tf32(Ab[ko + 4 + 16 * APITCH]);
            uint32_t b3 = f2tf32(Ab[ko + 4 + 24 * APITCH]);
            const int s = sbase + sl;
            const float2* wrow = g_Wf2 + (size_t)(s * 8) * 32 + lane;
#pragma unroll
            for (int nt = 0; nt < 8; nt++) {
                float2 wf = __ldg(wrow + nt * 32);
                uint32_t w0 = __float_as_uint(wf.x);
                uint32_t w1 = __float_as_uint(wf.y);
                mma_tf32(acc[0][nt], a0, a1, a2, a3, w0, w1);
                mma_tf32(acc[1][nt], b0, b1, b2, b3, w0, w1);
            }
        }

        if ((j & 15) == 15) {
            // Tile complete: epilogue from registers.
            const int tile = bid + (j >> 4) * grid;
            const int row0 = tile * TILE_M + arow;
            float* o0 = out + (size_t)row0 * ODIM + 2 * (lane & 3);
#pragma unroll
            for (int mb = 0; mb < 2; mb++) {
                float* om = o0 + (size_t)(mb * 16) * ODIM;
#pragma unroll
                for (int nt = 0; nt < 8; nt++) {
                    const int cb = nt * 8;
                    float2 v0 = {acc[mb][nt][0] + bias[nt].x,
                                 acc[mb][nt][1] + bias[nt].y};
                    float2 v1 = {acc[mb][nt][2] + bias[nt].x,
                                 acc[mb][nt][3] + bias[nt].y};
                    *(float2*)(om + cb)            = v0;
                    *(float2*)(om + cb + 8 * ODIM) = v1;
                    acc[mb][nt][0] = acc[mb][nt][1] = 0.0f;
                    acc[mb][nt][2] = acc[mb][nt][3] = 0.0f;
                }
            }
        }
    }
}

// ---------------------------------------------------------------------------
extern "C" void kernel_launch(void* const* d_in, const int* in_sizes, int n_in,
                              void* d_out, int out_size) {
    const float* x   = (const float*)d_in[0];
    const float* W   = (const float*)d_in[1];
    const float* b   = (const float*)d_in[2];
    const float* ps  = (const float*)d_in[3];
    const float* ent = (const float*)d_in[4];
    float* out = (float*)d_out;

    qnl_prep_kernel<<<33, 256>>>(b, ps, ent, W);

    cudaFuncSetAttribute(qnl_kernel,
                         cudaFuncAttributeMaxDynamicSharedMemorySize, SMEM_BYTES);

    int sm = 148;
    cudaDeviceGetAttribute(&sm, cudaDevAttrMultiProcessorCount, 0);
    int grid = sm < NTILES ? sm : NTILES;

    qnl_kernel<<<grid, NTHREADS, SMEM_BYTES>>>(x, out);
}

// round 6
// speedup vs baseline: 2.3823x; 2.3823x over previous
#include <cuda_runtime.h>
#include <cstdint>

// ============================================================================
// QuantumNeuralLayer: out = x @ W.T + (b + 0.1*q); q batch-independent.
// 262144x256x64 fp32 GEMM via mma.sync tf32.
// R6: barrier-free per-warp pipelines. Each warp cp.asyncs ONLY its own 32
// rows, so stage completion is warp-local (wait_group + syncwarp) and the
// whole-CTA __syncthreads per stage (R4's bubble source at occ=1) is gone.
// Warps free-run with skew; one warp's DRAM wait overlaps another's MMAs.
// ============================================================================

#define INV_SQRT2 0.70710678118654752440f

static constexpr int B_TOTAL = 262144;
static constexpr int KDIM    = 256;
static constexpr int ODIM    = 64;
static constexpr int TILE_M  = 256;                 // 8 warps x 32 rows
static constexpr int NTILES  = B_TOTAL / TILE_M;    // 1024
static constexpr int NTHREADS = 256;

static constexpr int KCHUNK   = 32;                 // floats per stage
static constexpr int SPT      = KDIM / KCHUNK;      // 8 stages per tile
static constexpr int APITCH   = 36;                 // floats; conflict-free
static constexpr int ASTAGE_F = TILE_M * APITCH;    // 9216 floats = 36 KB
static constexpr int WF_F     = 4 * ASTAGE_F;       // 36864
static constexpr int BIAS_F   = WF_F + 16384;       // 53248
static constexpr int HA_F     = BIAS_F + 64;
static constexpr int HC_F     = HA_F + 64;
static constexpr int SMEM_F   = HC_F + 64;
static constexpr int SMEM_BYTES = SMEM_F * 4;       // 213760 B

// ---------------------------------------------------------------------------
__device__ __forceinline__ uint32_t smem_u32(const void* p) {
    uint32_t a;
    asm("{ .reg .u64 t; cvta.to.shared.u64 t, %1; cvt.u32.u64 %0, t; }" : "=r"(a) : "l"(p));
    return a;
}
__device__ __forceinline__ void cp_async16(uint32_t s, const void* g) {
    asm volatile("cp.async.cg.shared.global [%0], [%1], 16;" :: "r"(s), "l"(g));
}
#define CP_COMMIT() asm volatile("cp.async.commit_group;" ::: "memory")
#define CP_WAIT_2() asm volatile("cp.async.wait_group 2;" ::: "memory")

__device__ __forceinline__ uint32_t f2tf32(float f) {
    uint32_t u;
    asm("cvt.rna.tf32.f32 %0, %1;" : "=r"(u) : "f"(f));
    return u;
}

__device__ __forceinline__ void mma_tf32(float c[4], uint32_t a0, uint32_t a1,
                                         uint32_t a2, uint32_t a3,
                                         uint32_t b0, uint32_t b1) {
    asm volatile(
        "mma.sync.aligned.m16n8k8.row.col.f32.tf32.tf32.f32 "
        "{%0,%1,%2,%3}, {%4,%5,%6,%7}, {%8,%9}, {%0,%1,%2,%3};"
        : "+f"(c[0]), "+f"(c[1]), "+f"(c[2]), "+f"(c[3])
        : "r"(a0), "r"(a1), "r"(a2), "r"(a3), "r"(b0), "r"(b1));
}

// ---------------------------------------------------------------------------
__global__ void __launch_bounds__(NTHREADS, 1)
qnl_kernel(const float* __restrict__ x, const float* __restrict__ W,
           const float* __restrict__ bvec, const float* __restrict__ phase,
           const float* __restrict__ ent, float* __restrict__ out) {
    extern __shared__ float smemf[];
    const uint32_t sb = smem_u32(smemf);
    const int tid  = threadIdx.x;
    const int wid  = tid >> 5;
    const int lane = tid & 31;
    const int grid = gridDim.x;
    const int bid  = blockIdx.x;

    // Warp owns rows [wid*32, wid*32+32); m-frags at +0 and +16.
    const int wrow = wid * 32;
    const int arow = wrow + (lane >> 2);

    const int ntile_local = (NTILES - bid + grid - 1) / grid;
    const int H = SPT * ntile_local;

    // Per-warp stage load: THIS warp's 32 rows of k-chunk (jq&7) of tile
    // (jq>>3), into ring slot jq&3. 256 x 16B chunks -> 8 per lane.
    auto load_stage = [&](int jq) {
        const int tile = bid + (jq >> 3) * grid;
        const float* src = x + (size_t)tile * TILE_M * KDIM + (jq & 7) * KCHUNK;
        const uint32_t abase = sb + (uint32_t)((jq & 3) * ASTAGE_F + wrow * APITCH) * 4;
#pragma unroll
        for (int i = 0; i < 8; i++) {
            int c  = lane + 32 * i;        // 0..255
            int r  = c >> 3;               // local row 0..31
            int kc = c & 7;                // 16B chunk within 32-float chunk
            cp_async16(abase + (uint32_t)(r * APITCH + kc * 4) * 4,
                       src + (size_t)(wrow + r) * KDIM + kc * 4);
        }
        CP_COMMIT();
    };

    // Prologue: fill 3 stages (per warp), prep Wf + bias under the latency.
    load_stage(0);
    load_stage(1);
    load_stage(2);

    // --- W fragments: tf32-rounded, layout [s(32)][nt(8)][lane(32)] float2 ---
    for (int e = tid; e < 8192; e += NTHREADS) {
        int le = e & 31;
        int nt = (e >> 5) & 7;
        int s  = e >> 8;
        int n = nt * 8 + (le >> 2);
        int k = s * 8 + (le & 3);
        float2 wf;
        wf.x = __uint_as_float(f2tf32(W[n * KDIM + k]));
        wf.y = __uint_as_float(f2tf32(W[n * KDIM + k + 4]));
        *(float2*)(smemf + WF_F + 2 * e) = wf;
    }

    // --- bias_eff = b + 0.1*quantum (batch-independent) ---
    {
        float a = 1.0f, c = 0.0f;
        for (int d = 0; d < 3; d++) {
            if (tid < 64) {
                float ph = phase[d * 64 + tid];
                smemf[HA_F + tid] = (a + c) * INV_SQRT2 * sinf(ph);
                smemf[HC_F + tid] = (a - c) * INV_SQRT2 * cosf(ph);
            }
            __syncthreads();
            if (tid < 64) {
                float sa = 0.0f, sc = 0.0f;
#pragma unroll
                for (int i = 0; i < 64; i++) {
                    float e = ent[i * 64 + tid];
                    sa += smemf[HA_F + i] * e;
                    sc += smemf[HC_F + i] * e;
                }
                a = sa; c = sc;
            }
            __syncthreads();
        }
        if (tid < 64) smemf[BIAS_F + tid] = bvec[tid] + 0.1f * (a * a + c * c);
    }
    __syncthreads();   // Wf + bias visible; ONLY CTA-wide barrier in kernel

    float2 bias[8];
#pragma unroll
    for (int nt = 0; nt < 8; nt++) {
        int col = nt * 8 + 2 * (lane & 3);
        bias[nt].x = smemf[BIAS_F + col];
        bias[nt].y = smemf[BIAS_F + col + 1];
    }

    float acc[2][8][4];
#pragma unroll
    for (int mb = 0; mb < 2; mb++)
#pragma unroll
        for (int nt = 0; nt < 8; nt++)
#pragma unroll
            for (int q = 0; q < 4; q++) acc[mb][nt][q] = 0.0f;

    const float2* Wb = (const float2*)(smemf + WF_F);

    for (int j = 0; j < H; j++) {
        CP_WAIT_2();       // this lane's stage-j chunks resident
        __syncwarp();      // whole warp's chunks resident (warp-local barrier)

        if (j + 3 < H) load_stage(j + 3);
        else CP_COMMIT();  // keep group accounting uniform

        const float* Ab = smemf + (j & 3) * ASTAGE_F + arow * APITCH + (lane & 3);
        const int sbase = (j & 7) * 4;

#pragma unroll
        for (int sl = 0; sl < 4; sl++) {
            const int ko = sl * 8;
            uint32_t a0 = f2tf32(Ab[ko]);
            uint32_t a1 = f2tf32(Ab[ko + 8 * APITCH]);
            uint32_t a2 = f2tf32(Ab[ko + 4]);
            uint32_t a3 = f2tf32(Ab[ko + 4 + 8 * APITCH]);
            uint32_t b0 = f2tf32(Ab[ko + 16 * APITCH]);
            uint32_t b1 = f2tf32(Ab[ko + 24 * APITCH]);
            uint32_t b2 = f2tf32(Ab[ko + 4 + 16 * APITCH]);
            uint32_t b3 = f2tf32(Ab[ko + 4 + 24 * APITCH]);
            const int s = sbase + sl;
#pragma unroll
            for (int nt = 0; nt < 8; nt++) {
                float2 wf = Wb[(s * 8 + nt) * 32 + lane];
                uint32_t w0 = __float_as_uint(wf.x);
                uint32_t w1 = __float_as_uint(wf.y);
                mma_tf32(acc[0][nt], a0, a1, a2, a3, w0, w1);
                mma_tf32(acc[1][nt], b0, b1, b2, b3, w0, w1);
            }
        }

        if ((j & 7) == 7) {
            // Tile complete: per-warp epilogue, no barriers.
            const int tile = bid + (j >> 3) * grid;
            const int row0 = tile * TILE_M + arow;
            float* o0 = out + (size_t)row0 * ODIM + 2 * (lane & 3);
#pragma unroll
            for (int mb = 0; mb < 2; mb++) {
                float* om = o0 + (size_t)(mb * 16) * ODIM;
#pragma unroll
                for (int nt = 0; nt < 8; nt++) {
                    const int cb = nt * 8;
                    float2 v0 = {acc[mb][nt][0] + bias[nt].x,
                                 acc[mb][nt][1] + bias[nt].y};
                    float2 v1 = {acc[mb][nt][2] + bias[nt].x,
                                 acc[mb][nt][3] + bias[nt].y};
                    *(float2*)(om + cb)            = v0;
                    *(float2*)(om + cb + 8 * ODIM) = v1;
                    acc[mb][nt][0] = acc[mb][nt][1] = 0.0f;
                    acc[mb][nt][2] = acc[mb][nt][3] = 0.0f;
                }
            }
        }
    }
}

// ---------------------------------------------------------------------------
extern "C" void kernel_launch(void* const* d_in, const int* in_sizes, int n_in,
                              void* d_out, int out_size) {
    const float* x   = (const float*)d_in[0];
    const float* W   = (const float*)d_in[1];
    const float* b   = (const float*)d_in[2];
    const float* ps  = (const float*)d_in[3];
    const float* ent = (const float*)d_in[4];
    float* out = (float*)d_out;

    cudaFuncSetAttribute(qnl_kernel,
                         cudaFuncAttributeMaxDynamicSharedMemorySize, SMEM_BYTES);

    int sm = 148;
    cudaDeviceGetAttribute(&sm, cudaDevAttrMultiProcessorCount, 0);
    int grid = sm < NTILES ? sm : NTILES;

    qnl_kernel<<<grid, NTHREADS, SMEM_BYTES>>>(x, W, b, ps, ent, out);
}